// round 2
// baseline (speedup 1.0000x reference)
#include <cuda_runtime.h>

typedef unsigned long long u64;

#define NN 50000
#define EE 1600000
#define GG 256
#define OUTC 10
#define SCAN_B 49          // ceil(50000/1024)
#define NCHUNK 1563        // ceil(50000/32)

// ---------------- device scratch ----------------
__device__ int g_cnt_row[NN], g_cnt_col[NN];
__device__ int g_off_row[NN], g_off_col[NN];
__device__ int g_cur_row[NN], g_cur_col[NN];
__device__ int g_bsum[2 * SCAN_B];
__device__ int g_csr_row_eid[EE];
__device__ int g_csr_col_src[EE];
__device__ float g_eagg[NN * 32];    // segment_sum(edge_attr, row) — layer-invariant
__device__ float g_yrel[NN * 64];    // xc @ W1r (pre-aggregation)
__device__ float g_hroot[NN * 64];   // relu(xc @ W1o + b1o)
__device__ float g_agg[NN * 64];     // aggregated y_rel
__device__ float g_xout[NN * 64];
__device__ float g_pooled[GG * 64];

// ---------------- f32x2 helpers ----------------
__device__ __forceinline__ u64 pack2(float lo, float hi) {
    u64 r; asm("mov.b64 %0, {%1,%2};" : "=l"(r) : "f"(lo), "f"(hi)); return r;
}
__device__ __forceinline__ void unpack2(u64 v, float& lo, float& hi) {
    asm("mov.b64 {%0,%1}, %2;" : "=f"(lo), "=f"(hi) : "l"(v));
}
__device__ __forceinline__ void ffma2(u64& d, u64 a, u64 b) {
    asm("fma.rn.f32x2 %0, %1, %2, %0;" : "+l"(d) : "l"(a), "l"(b));
}

// ---------------- CSR construction ----------------
__global__ void zero_k() {
    int i = blockIdx.x * blockDim.x + threadIdx.x;
    if (i < NN) { g_cnt_row[i] = 0; g_cnt_col[i] = 0; }
    if (i < GG * 64) g_pooled[i] = 0.f;
}

__global__ void count_k(const int* __restrict__ ei) {
    int e = blockIdx.x * blockDim.x + threadIdx.x;
    if (e < EE) {
        atomicAdd(&g_cnt_row[ei[e]], 1);
        atomicAdd(&g_cnt_col[ei[EE + e]], 1);
    }
}

__global__ void scan_p1() {
    __shared__ int s[1024];
    int arr = blockIdx.x / SCAN_B;
    int blk = blockIdx.x % SCAN_B;
    int i = blk * 1024 + threadIdx.x;
    const int* cnt = arr ? g_cnt_col : g_cnt_row;
    int* off = arr ? g_off_col : g_off_row;
    int v = (i < NN) ? cnt[i] : 0;
    s[threadIdx.x] = v;
    __syncthreads();
    for (int d = 1; d < 1024; d <<= 1) {
        int t = (threadIdx.x >= d) ? s[threadIdx.x - d] : 0;
        __syncthreads();
        s[threadIdx.x] += t;
        __syncthreads();
    }
    if (i < NN) off[i] = s[threadIdx.x] - v;
    if (threadIdx.x == 1023) g_bsum[blockIdx.x] = s[1023];
}

__global__ void scan_p2() {
    int a = threadIdx.x;
    if (a < 2) {
        int run = 0;
        for (int b = 0; b < SCAN_B; b++) {
            int t = g_bsum[a * SCAN_B + b];
            g_bsum[a * SCAN_B + b] = run;
            run += t;
        }
    }
}

__global__ void scan_p3() {
    int i = blockIdx.x * blockDim.x + threadIdx.x;
    if (i < NN) {
        int o = g_off_row[i] + g_bsum[i >> 10];
        g_off_row[i] = o; g_cur_row[i] = o;
    } else if (i < 2 * NN) {
        int idx = i - NN;
        int o = g_off_col[idx] + g_bsum[SCAN_B + (idx >> 10)];
        g_off_col[idx] = o; g_cur_col[idx] = o;
    }
}

__global__ void fill_k(const int* __restrict__ ei) {
    int e = blockIdx.x * blockDim.x + threadIdx.x;
    if (e < EE) {
        int r = ei[e], c = ei[EE + e];
        int p = atomicAdd(&g_cur_row[r], 1);
        g_csr_row_eid[p] = e;
        int q = atomicAdd(&g_cur_col[c], 1);
        g_csr_col_src[q] = r;
    }
}

// ---------------- edge-attr aggregation (once; layer-invariant) ----------------
__global__ void eagg_k(const float* __restrict__ ea) {
    int w = (blockIdx.x * blockDim.x + threadIdx.x) >> 5;
    int lane = threadIdx.x & 31;
    if (w >= NN) return;
    int s = g_off_row[w], c = g_cnt_row[w];
    float acc = 0.f;
    int eid_next = (c > 0) ? g_csr_row_eid[s] : 0;
    for (int k = 0; k < c; k++) {
        int eid = eid_next;
        if (k + 1 < c) eid_next = g_csr_row_eid[s + k + 1];
        acc += ea[eid * 32 + lane];
    }
    g_eagg[w * 32 + lane] = acc;
}

// ---------------- mlp_pre: y_rel = xc@W1r ; h_root = relu(xc@W1o + b1o) ----------------
#define PRE_WR 0        // 6144 floats
#define PRE_WO 6144     // 6144
#define PRE_IN 12288    // 3072 : [g][k][s] = g*768 + k*8 + s
#define PRE_SMEM ((12288 + 3072) * 4)

__global__ void mlp_pre_k(const float* __restrict__ xprev, int use_xout,
                          const float* __restrict__ W1r,
                          const float* __restrict__ W1o,
                          const float* __restrict__ b1o) {
    extern __shared__ float sm[];
    const float* xin = use_xout ? g_xout : xprev;
    int tid = threadIdx.x;
    for (int i = tid; i < 6144; i += 256) { sm[PRE_WR + i] = W1r[i]; sm[PRE_WO + i] = W1o[i]; }
    int j = tid & 63, grp = tid >> 6;
    float bo = b1o[j];
    __syncthreads();
    for (int chunk = blockIdx.x; chunk < NCHUNK; chunk += gridDim.x) {
        int base = chunk * 32;
        __syncthreads();
        for (int idx = tid; idx < 3072; idx += 256) {
            int nd = idx / 96, k = idx - nd * 96;
            int node = base + nd;
            float v = 0.f;
            if (node < NN) v = (k < 64) ? xin[node * 64 + k] : g_eagg[node * 32 + (k - 64)];
            sm[PRE_IN + (nd >> 3) * 768 + k * 8 + (nd & 7)] = v;
        }
        __syncthreads();
        u64 r0 = 0, r1 = 0, r2 = 0, r3 = 0;
        u64 bop = pack2(bo, bo);
        u64 o0 = bop, o1 = bop, o2 = bop, o3 = bop;
        const float* pin = &sm[PRE_IN + grp * 768];
        #pragma unroll 12
        for (int k = 0; k < 96; k++) {
            ulonglong2 va = *(const ulonglong2*)(pin + k * 8);
            ulonglong2 vb = *(const ulonglong2*)(pin + k * 8 + 4);
            float wrs = sm[PRE_WR + k * 64 + j];
            float wos = sm[PRE_WO + k * 64 + j];
            u64 wr = pack2(wrs, wrs), wo = pack2(wos, wos);
            ffma2(r0, va.x, wr); ffma2(r1, va.y, wr); ffma2(r2, vb.x, wr); ffma2(r3, vb.y, wr);
            ffma2(o0, va.x, wo); ffma2(o1, va.y, wo); ffma2(o2, vb.x, wo); ffma2(o3, vb.y, wo);
        }
        int nb = base + grp * 8;
        if (nb < NN) {     // 50000 % 8 == 0: group fully in-range or fully out
            float a, b;
            unpack2(r0, a, b); g_yrel[(nb + 0) * 64 + j] = a; g_yrel[(nb + 1) * 64 + j] = b;
            unpack2(r1, a, b); g_yrel[(nb + 2) * 64 + j] = a; g_yrel[(nb + 3) * 64 + j] = b;
            unpack2(r2, a, b); g_yrel[(nb + 4) * 64 + j] = a; g_yrel[(nb + 5) * 64 + j] = b;
            unpack2(r3, a, b); g_yrel[(nb + 6) * 64 + j] = a; g_yrel[(nb + 7) * 64 + j] = b;
            unpack2(o0, a, b); g_hroot[(nb + 0) * 64 + j] = fmaxf(a, 0.f); g_hroot[(nb + 1) * 64 + j] = fmaxf(b, 0.f);
            unpack2(o1, a, b); g_hroot[(nb + 2) * 64 + j] = fmaxf(a, 0.f); g_hroot[(nb + 3) * 64 + j] = fmaxf(b, 0.f);
            unpack2(o2, a, b); g_hroot[(nb + 4) * 64 + j] = fmaxf(a, 0.f); g_hroot[(nb + 5) * 64 + j] = fmaxf(b, 0.f);
            unpack2(o3, a, b); g_hroot[(nb + 6) * 64 + j] = fmaxf(a, 0.f); g_hroot[(nb + 7) * 64 + j] = fmaxf(b, 0.f);
        }
    }
}

// ---------------- gather: agg[n] = sum_{e: col==n} y_rel[row[e]] ----------------
__global__ void gather_k() {
    int w = (blockIdx.x * blockDim.x + threadIdx.x) >> 5;
    int lane = threadIdx.x & 31;
    if (w >= NN) return;
    int s = g_off_col[w], c = g_cnt_col[w];
    float ax = 0.f, ay = 0.f;
    int src_next = (c > 0) ? g_csr_col_src[s] : 0;
    for (int k = 0; k < c; k++) {
        int src = src_next;
        if (k + 1 < c) src_next = g_csr_col_src[s + k + 1];
        float2 v = *(const float2*)&g_yrel[src * 64 + lane * 2];
        ax += v.x; ay += v.y;
    }
    float2 o; o.x = ax; o.y = ay;
    *(float2*)&g_agg[w * 64 + lane * 2] = o;
}

// ------ mlp_post: xout = relu( relu(agg+b1r)@W2r + h_root@W2o + b2r+b2o ) ------
#define PO_WR 0       // 4096
#define PO_WO 4096    // 4096
#define PO_A  8192    // 2048 : [g][k][s] = g*512 + k*8 + s
#define PO_H  10240   // 2048
#define PO_B1 12288   // 64
#define PO_SMEM ((12288 + 64) * 4)

__global__ void mlp_post_k(const float* __restrict__ W2r, const float* __restrict__ b2r,
                           const float* __restrict__ W2o, const float* __restrict__ b2o,
                           const float* __restrict__ b1r,
                           const int* __restrict__ batch, int last) {
    extern __shared__ float sm[];
    int tid = threadIdx.x;
    for (int i = tid; i < 4096; i += 256) { sm[PO_WR + i] = W2r[i]; sm[PO_WO + i] = W2o[i]; }
    if (tid < 64) sm[PO_B1 + tid] = b1r[tid];
    int j = tid & 63, grp = tid >> 6;
    float b2 = b2r[j] + b2o[j];
    __syncthreads();
    for (int chunk = blockIdx.x; chunk < NCHUNK; chunk += gridDim.x) {
        int base = chunk * 32;
        __syncthreads();
        for (int idx = tid; idx < 2048; idx += 256) {
            int nd = idx >> 6, k = idx & 63;
            int node = base + nd;
            float a = 0.f, h = 0.f;
            if (node < NN) {
                a = fmaxf(g_agg[node * 64 + k] + sm[PO_B1 + k], 0.f);
                h = g_hroot[node * 64 + k];
            }
            sm[PO_A + (nd >> 3) * 512 + k * 8 + (nd & 7)] = a;
            sm[PO_H + (nd >> 3) * 512 + k * 8 + (nd & 7)] = h;
        }
        __syncthreads();
        u64 bp = pack2(b2, b2);
        u64 c0 = bp, c1 = bp, c2 = bp, c3 = bp;
        const float* pa = &sm[PO_A + grp * 512];
        const float* ph = &sm[PO_H + grp * 512];
        #pragma unroll 16
        for (int k = 0; k < 64; k++) {
            ulonglong2 va = *(const ulonglong2*)(pa + k * 8);
            ulonglong2 vb = *(const ulonglong2*)(pa + k * 8 + 4);
            ulonglong2 ha = *(const ulonglong2*)(ph + k * 8);
            ulonglong2 hb = *(const ulonglong2*)(ph + k * 8 + 4);
            float wrs = sm[PO_WR + k * 64 + j];
            float wos = sm[PO_WO + k * 64 + j];
            u64 wr = pack2(wrs, wrs), wo = pack2(wos, wos);
            ffma2(c0, va.x, wr); ffma2(c1, va.y, wr); ffma2(c2, vb.x, wr); ffma2(c3, vb.y, wr);
            ffma2(c0, ha.x, wo); ffma2(c1, ha.y, wo); ffma2(c2, hb.x, wo); ffma2(c3, hb.y, wo);
        }
        int nb = base + grp * 8;
        if (nb < NN) {
            float v[8];
            unpack2(c0, v[0], v[1]); unpack2(c1, v[2], v[3]);
            unpack2(c2, v[4], v[5]); unpack2(c3, v[6], v[7]);
            if (!last) {
                #pragma unroll
                for (int s = 0; s < 8; s++)
                    g_xout[(nb + s) * 64 + j] = fmaxf(v[s], 0.f);
            } else {
                #pragma unroll
                for (int s = 0; s < 8; s++)
                    atomicAdd(&g_pooled[batch[nb + s] * 64 + j], fmaxf(v[s], 0.f));
            }
        }
    }
}

// ---------------- final MLP ----------------
__global__ void fin_k(const float* __restrict__ W1, const float* __restrict__ b1,
                      const float* __restrict__ W2, const float* __restrict__ b2,
                      float* __restrict__ out) {
    __shared__ float p[64], h[64];
    int g = blockIdx.x, t = threadIdx.x;
    p[t] = g_pooled[g * 64 + t];
    __syncthreads();
    float a = b1[t];
    #pragma unroll
    for (int k = 0; k < 64; k++) a = fmaf(p[k], W1[k * 64 + t], a);
    h[t] = fmaxf(a, 0.f);
    __syncthreads();
    if (t < OUTC) {
        float o = b2[t];
        #pragma unroll
        for (int k = 0; k < 64; k++) o = fmaf(h[k], W2[k * OUTC + t], o);
        out[g * OUTC + t] = o;
    }
}

// ---------------- launch ----------------
extern "C" void kernel_launch(void* const* d_in, const int* in_sizes, int n_in,
                              void* d_out, int out_size) {
    const float* x  = (const float*)d_in[0];
    const float* ea = (const float*)d_in[1];
    const float* L[2][8];
    for (int l = 0; l < 2; l++)
        for (int i = 0; i < 8; i++)
            L[l][i] = (const float*)d_in[2 + l * 8 + i];
    const float* finW1 = (const float*)d_in[18];
    const float* finb1 = (const float*)d_in[19];
    const float* finW2 = (const float*)d_in[20];
    const float* finb2 = (const float*)d_in[21];
    const int* ei    = (const int*)d_in[22];
    const int* batch = (const int*)d_in[23];
    float* out = (float*)d_out;

    cudaFuncSetAttribute(mlp_pre_k, cudaFuncAttributeMaxDynamicSharedMemorySize, PRE_SMEM);
    cudaFuncSetAttribute(mlp_post_k, cudaFuncAttributeMaxDynamicSharedMemorySize, PO_SMEM);

    zero_k<<<(NN + 255) / 256, 256>>>();
    count_k<<<(EE + 255) / 256, 256>>>(ei);
    scan_p1<<<2 * SCAN_B, 1024>>>();
    scan_p2<<<1, 32>>>();
    scan_p3<<<(2 * NN + 255) / 256, 256>>>();
    fill_k<<<(EE + 255) / 256, 256>>>(ei);
    eagg_k<<<6250, 256>>>(ea);

    for (int l = 0; l < 2; l++) {
        mlp_pre_k<<<296, 256, PRE_SMEM>>>(x, l, L[l][0], L[l][4], L[l][5]);
        gather_k<<<6250, 256>>>();
        mlp_post_k<<<296, 256, PO_SMEM>>>(L[l][2], L[l][3], L[l][6], L[l][7],
                                          L[l][1], batch, l == 1);
    }
    fin_k<<<GG, 64>>>(finW1, finb1, finW2, finb2, out);
}

// round 4
// speedup vs baseline: 1.5730x; 1.5730x over previous
#include <cuda_runtime.h>

typedef unsigned long long u64;

#define NN 50000
#define EE 1600000
#define GG 256
#define OUTC 10
#define PAD 128
#define NCHUNK 1563        // ceil(50000/32)

// ---------------- device scratch ----------------
__device__ int g_cnt[2 * NN];          // [0:NN)=row counts, [NN:2NN)=col counts
__device__ int g_padr[NN * PAD];       // edge ids by source (row), padded bins
__device__ int g_padc[NN * PAD];       // source node ids by target (col), padded bins
__device__ float g_eagg[NN * 32];      // segment_sum(edge_attr, row) — layer-invariant
__device__ float g_yrel[NN * 64];      // xc @ W1r (pre-aggregation)
__device__ float g_hroot[NN * 64];     // relu(xc @ W1o + b1o)
__device__ float g_agg[NN * 64];       // aggregated y_rel
__device__ float g_xout[NN * 64];
__device__ float g_pooled[GG * 64];

// ---------------- f32x2 helpers ----------------
__device__ __forceinline__ u64 pack2(float lo, float hi) {
    u64 r; asm("mov.b64 %0, {%1,%2};" : "=l"(r) : "f"(lo), "f"(hi)); return r;
}
__device__ __forceinline__ void unpack2(u64 v, float& lo, float& hi) {
    asm("mov.b64 {%0,%1}, %2;" : "=f"(lo), "=f"(hi) : "l"(v));
}
__device__ __forceinline__ void ffma2(u64& d, u64 a, u64 b) {
    asm("fma.rn.f32x2 %0, %1, %2, %0;" : "+l"(d) : "l"(a), "l"(b));
}

// ---------------- padded-bin CSR fill (cnt pre-zeroed by memset) ----------------
__global__ void fill_k(const int* __restrict__ ei) {
    int e = blockIdx.x * blockDim.x + threadIdx.x;
    if (e < EE) {
        int r = ei[e], c = ei[EE + e];
        int p = atomicAdd(&g_cnt[r], 1);
        if (p < PAD) g_padr[r * PAD + p] = e;
        int q = atomicAdd(&g_cnt[NN + c], 1);
        if (q < PAD) g_padc[c * PAD + q] = r;
    }
}

// ---------------- edge-attr aggregation (once; layer-invariant) ----------------
__global__ void eagg_k(const float* __restrict__ ea) {
    int w = (blockIdx.x * blockDim.x + threadIdx.x) >> 5;
    int lane = threadIdx.x & 31;
    if (w >= NN) return;
    int c = min(g_cnt[w], PAD);
    const int* lst = &g_padr[w * PAD];
    float acc = 0.f;
    int k = 0;
    for (; k + 4 <= c; k += 4) {
        int e0 = lst[k], e1 = lst[k + 1], e2 = lst[k + 2], e3 = lst[k + 3];
        float v0 = ea[e0 * 32 + lane];
        float v1 = ea[e1 * 32 + lane];
        float v2 = ea[e2 * 32 + lane];
        float v3 = ea[e3 * 32 + lane];
        acc += (v0 + v1) + (v2 + v3);
    }
    for (; k < c; k++) acc += ea[lst[k] * 32 + lane];
    g_eagg[w * 32 + lane] = acc;
}

// ---------------- mlp_pre: y_rel = xc@W1r ; h_root = relu(xc@W1o + b1o) ----------------
#define PRE_WR 0        // 6144 floats
#define PRE_WO 6144     // 6144
#define PRE_IN 12288    // 3072 : [g][k][s] = g*768 + k*8 + s
#define PRE_SMEM ((12288 + 3072) * 4)

__global__ void mlp_pre_k(const float* __restrict__ xprev, int use_xout,
                          const float* __restrict__ W1r,
                          const float* __restrict__ W1o,
                          const float* __restrict__ b1o) {
    extern __shared__ float sm[];
    const float* xin = use_xout ? g_xout : xprev;
    int tid = threadIdx.x;
    for (int i = tid; i < 6144; i += 256) { sm[PRE_WR + i] = W1r[i]; sm[PRE_WO + i] = W1o[i]; }
    int j = tid & 63, grp = tid >> 6;
    float bo = b1o[j];
    __syncthreads();
    for (int chunk = blockIdx.x; chunk < NCHUNK; chunk += gridDim.x) {
        int base = chunk * 32;
        __syncthreads();
        for (int idx = tid; idx < 3072; idx += 256) {
            int nd = idx / 96, k = idx - nd * 96;
            int node = base + nd;
            float v = 0.f;
            if (node < NN) v = (k < 64) ? xin[node * 64 + k] : g_eagg[node * 32 + (k - 64)];
            sm[PRE_IN + (nd >> 3) * 768 + k * 8 + (nd & 7)] = v;
        }
        __syncthreads();
        u64 r0 = 0, r1 = 0, r2 = 0, r3 = 0;
        u64 bop = pack2(bo, bo);
        u64 o0 = bop, o1 = bop, o2 = bop, o3 = bop;
        const float* pin = &sm[PRE_IN + grp * 768];
        #pragma unroll 12
        for (int k = 0; k < 96; k++) {
            ulonglong2 va = *(const ulonglong2*)(pin + k * 8);
            ulonglong2 vb = *(const ulonglong2*)(pin + k * 8 + 4);
            float wrs = sm[PRE_WR + k * 64 + j];
            float wos = sm[PRE_WO + k * 64 + j];
            u64 wr = pack2(wrs, wrs), wo = pack2(wos, wos);
            ffma2(r0, va.x, wr); ffma2(r1, va.y, wr); ffma2(r2, vb.x, wr); ffma2(r3, vb.y, wr);
            ffma2(o0, va.x, wo); ffma2(o1, va.y, wo); ffma2(o2, vb.x, wo); ffma2(o3, vb.y, wo);
        }
        int nb = base + grp * 8;
        if (nb < NN) {     // 50000 % 8 == 0: group fully in-range or fully out
            float a, b;
            unpack2(r0, a, b); g_yrel[(nb + 0) * 64 + j] = a; g_yrel[(nb + 1) * 64 + j] = b;
            unpack2(r1, a, b); g_yrel[(nb + 2) * 64 + j] = a; g_yrel[(nb + 3) * 64 + j] = b;
            unpack2(r2, a, b); g_yrel[(nb + 4) * 64 + j] = a; g_yrel[(nb + 5) * 64 + j] = b;
            unpack2(r3, a, b); g_yrel[(nb + 6) * 64 + j] = a; g_yrel[(nb + 7) * 64 + j] = b;
            unpack2(o0, a, b); g_hroot[(nb + 0) * 64 + j] = fmaxf(a, 0.f); g_hroot[(nb + 1) * 64 + j] = fmaxf(b, 0.f);
            unpack2(o1, a, b); g_hroot[(nb + 2) * 64 + j] = fmaxf(a, 0.f); g_hroot[(nb + 3) * 64 + j] = fmaxf(b, 0.f);
            unpack2(o2, a, b); g_hroot[(nb + 4) * 64 + j] = fmaxf(a, 0.f); g_hroot[(nb + 5) * 64 + j] = fmaxf(b, 0.f);
            unpack2(o3, a, b); g_hroot[(nb + 6) * 64 + j] = fmaxf(a, 0.f); g_hroot[(nb + 7) * 64 + j] = fmaxf(b, 0.f);
        }
    }
}

// ---------------- gather: agg[n] = sum_{e: col==n} y_rel[row[e]] ----------------
__global__ void gather_k() {
    int w = (blockIdx.x * blockDim.x + threadIdx.x) >> 5;
    int lane = threadIdx.x & 31;
    if (w >= NN) return;
    int c = min(g_cnt[NN + w], PAD);
    const int* lst = &g_padc[w * PAD];
    float ax = 0.f, ay = 0.f;
    int k = 0;
    for (; k + 4 <= c; k += 4) {
        int s0 = lst[k], s1 = lst[k + 1], s2 = lst[k + 2], s3 = lst[k + 3];
        float2 v0 = *(const float2*)&g_yrel[s0 * 64 + lane * 2];
        float2 v1 = *(const float2*)&g_yrel[s1 * 64 + lane * 2];
        float2 v2 = *(const float2*)&g_yrel[s2 * 64 + lane * 2];
        float2 v3 = *(const float2*)&g_yrel[s3 * 64 + lane * 2];
        ax += (v0.x + v1.x) + (v2.x + v3.x);
        ay += (v0.y + v1.y) + (v2.y + v3.y);
    }
    for (; k < c; k++) {
        float2 v = *(const float2*)&g_yrel[lst[k] * 64 + lane * 2];
        ax += v.x; ay += v.y;
    }
    float2 o; o.x = ax; o.y = ay;
    *(float2*)&g_agg[w * 64 + lane * 2] = o;
}

// ------ mlp_post: xout = relu( relu(agg+b1r)@W2r + h_root@W2o + b2r+b2o ) ------
#define PO_WR 0       // 4096
#define PO_WO 4096    // 4096
#define PO_A  8192    // 2048 : [g][k][s] = g*512 + k*8 + s
#define PO_H  10240   // 2048
#define PO_B1 12288   // 64
#define PO_SMEM ((12288 + 64) * 4)

__global__ void mlp_post_k(const float* __restrict__ W2r, const float* __restrict__ b2r,
                           const float* __restrict__ W2o, const float* __restrict__ b2o,
                           const float* __restrict__ b1r,
                           const int* __restrict__ batch, int last) {
    extern __shared__ float sm[];
    int tid = threadIdx.x;
    for (int i = tid; i < 4096; i += 256) { sm[PO_WR + i] = W2r[i]; sm[PO_WO + i] = W2o[i]; }
    if (tid < 64) sm[PO_B1 + tid] = b1r[tid];
    int j = tid & 63, grp = tid >> 6;
    float b2 = b2r[j] + b2o[j];
    __syncthreads();
    for (int chunk = blockIdx.x; chunk < NCHUNK; chunk += gridDim.x) {
        int base = chunk * 32;
        __syncthreads();
        for (int idx = tid; idx < 2048; idx += 256) {
            int nd = idx >> 6, k = idx & 63;
            int node = base + nd;
            float a = 0.f, h = 0.f;
            if (node < NN) {
                a = fmaxf(g_agg[node * 64 + k] + sm[PO_B1 + k], 0.f);
                h = g_hroot[node * 64 + k];
            }
            sm[PO_A + (nd >> 3) * 512 + k * 8 + (nd & 7)] = a;
            sm[PO_H + (nd >> 3) * 512 + k * 8 + (nd & 7)] = h;
        }
        __syncthreads();
        u64 bp = pack2(b2, b2);
        u64 c0 = bp, c1 = bp, c2 = bp, c3 = bp;
        const float* pa = &sm[PO_A + grp * 512];
        const float* ph = &sm[PO_H + grp * 512];
        #pragma unroll 16
        for (int k = 0; k < 64; k++) {
            ulonglong2 va = *(const ulonglong2*)(pa + k * 8);
            ulonglong2 vb = *(const ulonglong2*)(pa + k * 8 + 4);
            ulonglong2 ha = *(const ulonglong2*)(ph + k * 8);
            ulonglong2 hb = *(const ulonglong2*)(ph + k * 8 + 4);
            float wrs = sm[PO_WR + k * 64 + j];
            float wos = sm[PO_WO + k * 64 + j];
            u64 wr = pack2(wrs, wrs), wo = pack2(wos, wos);
            ffma2(c0, va.x, wr); ffma2(c1, va.y, wr); ffma2(c2, vb.x, wr); ffma2(c3, vb.y, wr);
            ffma2(c0, ha.x, wo); ffma2(c1, ha.y, wo); ffma2(c2, hb.x, wo); ffma2(c3, hb.y, wo);
        }
        int nb = base + grp * 8;
        if (nb < NN) {
            float v[8];
            unpack2(c0, v[0], v[1]); unpack2(c1, v[2], v[3]);
            unpack2(c2, v[4], v[5]); unpack2(c3, v[6], v[7]);
            if (!last) {
                #pragma unroll
                for (int s = 0; s < 8; s++)
                    g_xout[(nb + s) * 64 + j] = fmaxf(v[s], 0.f);
            } else {
                #pragma unroll
                for (int s = 0; s < 8; s++)
                    atomicAdd(&g_pooled[batch[nb + s] * 64 + j], fmaxf(v[s], 0.f));
            }
        }
    }
}

// ---------------- final MLP ----------------
__global__ void fin_k(const float* __restrict__ W1, const float* __restrict__ b1,
                      const float* __restrict__ W2, const float* __restrict__ b2,
                      float* __restrict__ out) {
    __shared__ float p[64], h[64];
    int g = blockIdx.x, t = threadIdx.x;
    p[t] = g_pooled[g * 64 + t];
    __syncthreads();
    float a = b1[t];
    #pragma unroll
    for (int k = 0; k < 64; k++) a = fmaf(p[k], W1[k * 64 + t], a);
    h[t] = fmaxf(a, 0.f);
    __syncthreads();
    if (t < OUTC) {
        float o = b2[t];
        #pragma unroll
        for (int k = 0; k < 64; k++) o = fmaf(h[k], W2[k * OUTC + t], o);
        out[g * OUTC + t] = o;
    }
}

// ---------------- launch ----------------
extern "C" void kernel_launch(void* const* d_in, const int* in_sizes, int n_in,
                              void* d_out, int out_size) {
    const float* x  = (const float*)d_in[0];
    const float* ea = (const float*)d_in[1];
    const float* L[2][8];
    for (int l = 0; l < 2; l++)
        for (int i = 0; i < 8; i++)
            L[l][i] = (const float*)d_in[2 + l * 8 + i];
    const float* finW1 = (const float*)d_in[18];
    const float* finb1 = (const float*)d_in[19];
    const float* finW2 = (const float*)d_in[20];
    const float* finb2 = (const float*)d_in[21];
    const int* ei    = (const int*)d_in[22];
    const int* batch = (const int*)d_in[23];
    float* out = (float*)d_out;

    cudaFuncSetAttribute(mlp_pre_k, cudaFuncAttributeMaxDynamicSharedMemorySize, PRE_SMEM);
    cudaFuncSetAttribute(mlp_post_k, cudaFuncAttributeMaxDynamicSharedMemorySize, PO_SMEM);

    void* cntp = 0; void* poolp = 0;
    cudaGetSymbolAddress(&cntp, g_cnt);
    cudaGetSymbolAddress(&poolp, g_pooled);
    cudaMemsetAsync(cntp, 0, 2 * NN * sizeof(int));
    cudaMemsetAsync(poolp, 0, GG * 64 * sizeof(float));

    fill_k<<<(EE + 255) / 256, 256>>>(ei);
    eagg_k<<<6250, 256>>>(ea);

    for (int l = 0; l < 2; l++) {
        mlp_pre_k<<<444, 256, PRE_SMEM>>>(x, l, L[l][0], L[l][4], L[l][5]);
        gather_k<<<6250, 256>>>();
        mlp_post_k<<<592, 256, PO_SMEM>>>(L[l][2], L[l][3], L[l][6], L[l][7],
                                          L[l][1], batch, l == 1);
    }
    fin_k<<<GG, 64>>>(finW1, finb1, finW2, finb2, out);
}